// round 2
// baseline (speedup 1.0000x reference)
#include <cuda_runtime.h>

// GCN: 2x GCNConv (sym-norm, self-loops) + ReLU + final linear.
// N=100000 nodes, E=3.2M edges, IN_DIM=128, dims 128->32->16->1.

#define NMAX 100000
#define EMAX 3200000

// Scratch (allocation-free rule: __device__ globals)
__device__ int   g_is64;
__device__ __align__(16) int   g_src [EMAX];
__device__ __align__(16) int   g_dst [EMAX];
__device__ __align__(16) float g_deg [NMAX];
__device__ __align__(16) float g_dinv[NMAX];
__device__ __align__(16) float g_h1  [NMAX * 32];
__device__ __align__(16) float g_a1  [NMAX * 32];
__device__ __align__(16) float g_h2  [NMAX * 16];
__device__ __align__(16) float g_a2  [NMAX * 16];

// -------------------------------------------------- index dtype detection
// int64 claim is only true if reading as int64 yields in-range values.
// For int32 data read as int64, the high word is a uniform value in [0,1e5),
// so 16 consecutive in-range values is conclusive.
__global__ void k_detect(const void* ei, int N) {
    const long long* p = (const long long*)ei;
    int ok = 1;
    for (int i = 0; i < 16; i++) {
        long long v = p[i];
        if (v < 0 || v >= N) ok = 0;
    }
    g_is64 = ok;
}

__global__ void k_convert(const void* ei, int E) {
    int e = blockIdx.x * blockDim.x + threadIdx.x;
    if (e >= E) return;
    int s, d;
    if (g_is64) {
        const long long* p = (const long long*)ei;
        s = (int)p[e];
        d = (int)p[(long long)E + e];
    } else {
        const int* p = (const int*)ei;
        s = p[e];
        d = p[E + e];
    }
    g_src[e] = s;
    g_dst[e] = d;
}

// ---------------------------------------------------------------- degree
__global__ void k_deg_init(int N) {
    int i = blockIdx.x * blockDim.x + threadIdx.x;
    if (i < N) g_deg[i] = 1.0f;   // self-loop
}

__global__ void k_deg_acc(int E) {
    int e = blockIdx.x * blockDim.x + threadIdx.x;
    if (e < E) atomicAdd(&g_deg[g_dst[e]], 1.0f);
}

// ------------------------------------------- GEMM1 (x@W1) + dinv + a1 init
// block = 256 threads, 32 nodes/block. smem: W1 (128x32) + x tile (32x128, padded)
__global__ __launch_bounds__(256) void k_gemm1(const float* __restrict__ x,
                                               const float* __restrict__ W1,
                                               const float* __restrict__ b1,
                                               int N) {
    __shared__ float Ws[128 * 32];
    __shared__ float xs[32 * 129];
    int t = threadIdx.x;
    for (int i = t; i < 128 * 32; i += 256) Ws[i] = W1[i];
    int base = blockIdx.x * 32;
    for (int i = t; i < 32 * 128; i += 256) {
        int n = i >> 7, k = i & 127;
        int node = base + n;
        xs[n * 129 + k] = (node < N) ? x[(long long)node * 128 + k] : 0.0f;
    }
    __syncthreads();

    int f4 = t & 7;      // 8 groups of 4 output features
    int n  = t >> 3;     // 32 nodes
    int node = base + n;

    float4 acc = make_float4(0.f, 0.f, 0.f, 0.f);
    const float4* Ws4 = (const float4*)Ws;
#pragma unroll 8
    for (int k = 0; k < 128; k++) {
        float   xv = xs[n * 129 + k];
        float4  w  = Ws4[k * 8 + f4];
        acc.x += xv * w.x; acc.y += xv * w.y;
        acc.z += xv * w.z; acc.w += xv * w.w;
    }
    if (node < N) {
        float dv = rsqrtf(g_deg[node]);
        if (f4 == 0) g_dinv[node] = dv;
        float s = dv * dv;                       // self-loop norm
        float4 bb = ((const float4*)b1)[f4];
        ((float4*)g_h1)[(long long)node * 8 + f4] = acc;
        float4 a;
        a.x = acc.x * s + bb.x; a.y = acc.y * s + bb.y;
        a.z = acc.z * s + bb.z; a.w = acc.w * s + bb.w;
        ((float4*)g_a1)[(long long)node * 8 + f4] = a;
    }
}

// ---------------------------------------------------- edge scatter, layer 1
// 8 threads per edge, each handles 4 of the 32 features (float4 + red.v4)
__global__ __launch_bounds__(256) void k_edge1(int E) {
    int idx = blockIdx.x * blockDim.x + threadIdx.x;
    int e = idx >> 3, c = idx & 7;
    if (e >= E) return;
    int s = g_src[e];
    int d = g_dst[e];
    float norm = g_dinv[s] * g_dinv[d];
    float4 v = ((const float4*)g_h1)[(long long)s * 8 + c];
    v.x *= norm; v.y *= norm; v.z *= norm; v.w *= norm;
    float* p = &g_a1[(long long)d * 32 + c * 4];
    unsigned long long gp = (unsigned long long)__cvta_generic_to_global(p);
    asm volatile("red.global.add.v4.f32 [%0], {%1, %2, %3, %4};"
                 :: "l"(gp), "f"(v.x), "f"(v.y), "f"(v.z), "f"(v.w) : "memory");
}

// --------------------------------- GEMM2 (relu(a1)@W2) + a2 init (self-loop)
// block = 256 threads, 64 nodes/block, 4 threads per node (4 feats each)
__global__ __launch_bounds__(256) void k_gemm2(const float* __restrict__ W2,
                                               const float* __restrict__ b2,
                                               int N) {
    __shared__ float Ws[32 * 16];
    int t = threadIdx.x;
    for (int i = t; i < 32 * 16; i += 256) Ws[i] = W2[i];
    __syncthreads();

    int f4 = t & 3;
    int n  = blockIdx.x * 64 + (t >> 2);
    if (n >= N) return;

    float4 acc = make_float4(0.f, 0.f, 0.f, 0.f);
    const float4* a1r = (const float4*)(g_a1 + (long long)n * 32);
    const float4* Ws4 = (const float4*)Ws;   // Ws4[k*4 + f4] = W2[k][4f4..]
#pragma unroll
    for (int k4 = 0; k4 < 8; k4++) {
        float4 av = a1r[k4];
        float xv0 = fmaxf(av.x, 0.f), xv1 = fmaxf(av.y, 0.f);
        float xv2 = fmaxf(av.z, 0.f), xv3 = fmaxf(av.w, 0.f);
        float4 w0 = Ws4[(k4 * 4 + 0) * 4 + f4];
        float4 w1 = Ws4[(k4 * 4 + 1) * 4 + f4];
        float4 w2 = Ws4[(k4 * 4 + 2) * 4 + f4];
        float4 w3 = Ws4[(k4 * 4 + 3) * 4 + f4];
        acc.x += xv0 * w0.x + xv1 * w1.x + xv2 * w2.x + xv3 * w3.x;
        acc.y += xv0 * w0.y + xv1 * w1.y + xv2 * w2.y + xv3 * w3.y;
        acc.z += xv0 * w0.z + xv1 * w1.z + xv2 * w2.z + xv3 * w3.z;
        acc.w += xv0 * w0.w + xv1 * w1.w + xv2 * w2.w + xv3 * w3.w;
    }
    float dv = g_dinv[n];
    float s  = dv * dv;
    float4 bb = ((const float4*)b2)[f4];
    ((float4*)g_h2)[(long long)n * 4 + f4] = acc;
    float4 a;
    a.x = acc.x * s + bb.x; a.y = acc.y * s + bb.y;
    a.z = acc.z * s + bb.z; a.w = acc.w * s + bb.w;
    ((float4*)g_a2)[(long long)n * 4 + f4] = a;
}

// ---------------------------------------------------- edge scatter, layer 2
// 4 threads per edge, each handles 4 of the 16 features
__global__ __launch_bounds__(256) void k_edge2(int E) {
    int idx = blockIdx.x * blockDim.x + threadIdx.x;
    int e = idx >> 2, c = idx & 3;
    if (e >= E) return;
    int s = g_src[e];
    int d = g_dst[e];
    float norm = g_dinv[s] * g_dinv[d];
    float4 v = ((const float4*)g_h2)[(long long)s * 4 + c];
    v.x *= norm; v.y *= norm; v.z *= norm; v.w *= norm;
    float* p = &g_a2[(long long)d * 16 + c * 4];
    unsigned long long gp = (unsigned long long)__cvta_generic_to_global(p);
    asm volatile("red.global.add.v4.f32 [%0], {%1, %2, %3, %4};"
                 :: "l"(gp), "f"(v.x), "f"(v.y), "f"(v.z), "f"(v.w) : "memory");
}

// --------------------------------------------------------- final projection
__global__ __launch_bounds__(256) void k_final(const float* __restrict__ Wf,
                                               const float* __restrict__ bf,
                                               float* __restrict__ out, int N) {
    int n = blockIdx.x * blockDim.x + threadIdx.x;
    if (n >= N) return;
    const float4* a = (const float4*)(g_a2 + (long long)n * 16);
    float acc = 0.f;
#pragma unroll
    for (int k4 = 0; k4 < 4; k4++) {
        float4 v = a[k4];
        acc += fmaxf(v.x, 0.f) * __ldg(&Wf[k4 * 4 + 0]);
        acc += fmaxf(v.y, 0.f) * __ldg(&Wf[k4 * 4 + 1]);
        acc += fmaxf(v.z, 0.f) * __ldg(&Wf[k4 * 4 + 2]);
        acc += fmaxf(v.w, 0.f) * __ldg(&Wf[k4 * 4 + 3]);
    }
    out[n] = acc + __ldg(&bf[0]);
}

// ---------------------------------------------------------------- launcher
extern "C" void kernel_launch(void* const* d_in, const int* in_sizes, int n_in,
                              void* d_out, int out_size) {
    const float* x  = (const float*)d_in[0];
    const void*  ei = d_in[1];
    const float* W1 = (const float*)d_in[2];
    const float* b1 = (const float*)d_in[3];
    const float* W2 = (const float*)d_in[4];
    const float* b2 = (const float*)d_in[5];
    const float* Wf = (const float*)d_in[6];
    const float* bf = (const float*)d_in[7];
    float* out = (float*)d_out;

    int N = in_sizes[0] / 128;   // 100000
    int E = in_sizes[1] / 2;     // 3200000

    k_detect  <<<1, 1>>>(ei, N);
    k_convert <<<(E + 255) / 256, 256>>>(ei, E);
    k_deg_init<<<(N + 255) / 256, 256>>>(N);
    k_deg_acc <<<(E + 255) / 256, 256>>>(E);
    k_gemm1   <<<(N + 31) / 32, 256>>>(x, W1, b1, N);
    {
        long long T = (long long)E * 8;
        k_edge1<<<(unsigned)((T + 255) / 256), 256>>>(E);
    }
    k_gemm2   <<<(N + 63) / 64, 256>>>(W2, b2, N);
    {
        long long T = (long long)E * 4;
        k_edge2<<<(unsigned)((T + 255) / 256), 256>>>(E);
    }
    k_final   <<<(N + 255) / 256, 256>>>(Wf, bf, out, N);
}

// round 3
// speedup vs baseline: 1.3104x; 1.3104x over previous
#include <cuda_runtime.h>

// GCN: 2x GCNConv (sym-norm, self-loops) + ReLU + final linear.
// N=100000, E=3.2M, dims 128->32->16->1.
// Strategy: CSR-by-dst built per replay; norm factored as dinv[s]*dinv[d] with
// features pre-scaled by dinv -> aggregation is pure gather+register-sum, no
// feature atomics.

#define NMAX 100000
#define EMAX 3200000
#define SCAN_B 512
#define NBLK ((NMAX + SCAN_B - 1) / SCAN_B)

__device__ int g_is64;
__device__ __align__(16) int   g_src [EMAX];
__device__ __align__(16) int   g_dst [EMAX];
__device__ __align__(16) int   g_csr [EMAX];
__device__ __align__(16) int   g_cnt [NMAX];
__device__ __align__(16) int   g_rowp[NMAX];
__device__ __align__(16) int   g_wcur[NMAX];
__device__ __align__(16) int   g_bsum[NBLK];
__device__ __align__(16) int   g_boff[NBLK];
__device__ __align__(16) float g_dinv[NMAX];
__device__ __align__(16) float g_h1  [NMAX * 32];   // dinv-prescaled x@W1
__device__ __align__(16) float g_a1  [NMAX * 32];   // relu(agg1)
__device__ __align__(16) float g_h2  [NMAX * 16];   // dinv-prescaled a1@W2

// ---------------------------------------------------------------- init/detect
__global__ void k_zero_cnt(int N) {
    int i = blockIdx.x * blockDim.x + threadIdx.x;
    if (i < N) g_cnt[i] = 0;
}

// int32 data read as int64 has a uniform [0,1e5) value in the high word ->
// 16 consecutive in-range int64 reads is conclusive for genuine int64.
__global__ void k_detect(const void* ei, int N) {
    const long long* p = (const long long*)ei;
    int ok = 1;
    for (int i = 0; i < 16; i++) {
        long long v = p[i];
        if (v < 0 || v >= N) ok = 0;
    }
    g_is64 = ok;
}

// ------------------------------------- convert to int32 + dst-degree count
__global__ void k_convert(const void* ei, int E) {
    int e = blockIdx.x * blockDim.x + threadIdx.x;
    if (e >= E) return;
    int s, d;
    if (g_is64) {
        const long long* p = (const long long*)ei;
        s = (int)p[e];
        d = (int)p[(long long)E + e];
    } else {
        const int* p = (const int*)ei;
        s = p[e];
        d = p[E + e];
    }
    g_src[e] = s;
    g_dst[e] = d;
    atomicAdd(&g_cnt[d], 1);
}

// ------------------------------------------------------------ prefix scan
__global__ __launch_bounds__(SCAN_B) void k_scan1(int N) {
    __shared__ int sm[SCAN_B];
    int t = threadIdx.x;
    int i = blockIdx.x * SCAN_B + t;
    int v = (i < N) ? g_cnt[i] : 0;
    int acc = v;
    sm[t] = acc;
    __syncthreads();
    for (int off = 1; off < SCAN_B; off <<= 1) {
        int add = (t >= off) ? sm[t - off] : 0;
        __syncthreads();
        acc += add;
        sm[t] = acc;
        __syncthreads();
    }
    if (i < N) g_rowp[i] = acc - v;            // block-local exclusive
    if (t == SCAN_B - 1) g_bsum[blockIdx.x] = acc;
}

__global__ __launch_bounds__(256) void k_scan2(int NB) {
    __shared__ int sm[256];
    int t = threadIdx.x;
    int v = (t < NB) ? g_bsum[t] : 0;
    int acc = v;
    sm[t] = acc;
    __syncthreads();
    for (int off = 1; off < 256; off <<= 1) {
        int add = (t >= off) ? sm[t - off] : 0;
        __syncthreads();
        acc += add;
        sm[t] = acc;
        __syncthreads();
    }
    if (t < NB) g_boff[t] = acc - v;           // exclusive block offsets
}

__global__ void k_scan3(int N) {
    int i = blockIdx.x * blockDim.x + threadIdx.x;
    if (i < N) {
        int r = g_rowp[i] + g_boff[i / SCAN_B];
        g_rowp[i] = r;
        g_wcur[i] = r;
    }
}

// --------------------------------------------------------- CSR edge scatter
__global__ void k_scatter(int E) {
    int e = blockIdx.x * blockDim.x + threadIdx.x;
    if (e >= E) return;
    int d = g_dst[e];
    int pos = atomicAdd(&g_wcur[d], 1);
    g_csr[pos] = g_src[e];
}

// --------------------------- GEMM1: h1s = dinv * (x @ W1); also write dinv
__global__ __launch_bounds__(256) void k_gemm1(const float* __restrict__ x,
                                               const float* __restrict__ W1,
                                               int N) {
    __shared__ float Ws[128 * 32];
    __shared__ float xs[32 * 129];
    int t = threadIdx.x;
    for (int i = t; i < 128 * 32; i += 256) Ws[i] = W1[i];
    int base = blockIdx.x * 32;
    for (int i = t; i < 32 * 128; i += 256) {
        int n = i >> 7, k = i & 127;
        int node = base + n;
        xs[n * 129 + k] = (node < N) ? x[(long long)node * 128 + k] : 0.0f;
    }
    __syncthreads();

    int f4 = t & 7;
    int n  = t >> 3;
    int node = base + n;

    float4 acc = make_float4(0.f, 0.f, 0.f, 0.f);
    const float4* Ws4 = (const float4*)Ws;
#pragma unroll 8
    for (int k = 0; k < 128; k++) {
        float  xv = xs[n * 129 + k];
        float4 w  = Ws4[k * 8 + f4];
        acc.x += xv * w.x; acc.y += xv * w.y;
        acc.z += xv * w.z; acc.w += xv * w.w;
    }
    if (node < N) {
        float dv = rsqrtf((float)(g_cnt[node] + 1));   // +1 self-loop
        if (f4 == 0) g_dinv[node] = dv;
        acc.x *= dv; acc.y *= dv; acc.z *= dv; acc.w *= dv;
        ((float4*)g_h1)[(long long)node * 8 + f4] = acc;
    }
}

// ----------------- agg layer1: a1 = relu(dinv*(h1s[self]+sum h1s[nbr]) + b1)
// 8 threads per node, float4 each (32 features)
__global__ __launch_bounds__(256) void k_agg1(const float* __restrict__ b1, int N) {
    int idx = blockIdx.x * blockDim.x + threadIdx.x;
    int n = idx >> 3, c = idx & 7;
    if (n >= N) return;
    int beg = g_rowp[n];
    int end = beg + g_cnt[n];
    float4 acc = ((const float4*)g_h1)[(long long)n * 8 + c];   // self term
    for (int j = beg; j < end; j++) {
        int s = g_csr[j];
        float4 v = ((const float4*)g_h1)[(long long)s * 8 + c];
        acc.x += v.x; acc.y += v.y; acc.z += v.z; acc.w += v.w;
    }
    float dv = g_dinv[n];
    float4 bb = ((const float4*)b1)[c];
    float4 r;
    r.x = fmaxf(acc.x * dv + bb.x, 0.f);
    r.y = fmaxf(acc.y * dv + bb.y, 0.f);
    r.z = fmaxf(acc.z * dv + bb.z, 0.f);
    r.w = fmaxf(acc.w * dv + bb.w, 0.f);
    ((float4*)g_a1)[(long long)n * 8 + c] = r;
}

// --------------------------------- GEMM2: h2s = dinv * (a1 @ W2)
// 64 nodes/block, 4 threads/node (4 feats each)
__global__ __launch_bounds__(256) void k_gemm2(const float* __restrict__ W2, int N) {
    __shared__ float Ws[32 * 16];
    int t = threadIdx.x;
    for (int i = t; i < 32 * 16; i += 256) Ws[i] = W2[i];
    __syncthreads();

    int f4 = t & 3;
    int n  = blockIdx.x * 64 + (t >> 2);
    if (n >= N) return;

    float4 acc = make_float4(0.f, 0.f, 0.f, 0.f);
    const float4* a1r = (const float4*)(g_a1 + (long long)n * 32);
    const float4* Ws4 = (const float4*)Ws;
#pragma unroll
    for (int k4 = 0; k4 < 8; k4++) {
        float4 av = a1r[k4];
        float4 w0 = Ws4[(k4 * 4 + 0) * 4 + f4];
        float4 w1 = Ws4[(k4 * 4 + 1) * 4 + f4];
        float4 w2 = Ws4[(k4 * 4 + 2) * 4 + f4];
        float4 w3 = Ws4[(k4 * 4 + 3) * 4 + f4];
        acc.x += av.x * w0.x + av.y * w1.x + av.z * w2.x + av.w * w3.x;
        acc.y += av.x * w0.y + av.y * w1.y + av.z * w2.y + av.w * w3.y;
        acc.z += av.x * w0.z + av.y * w1.z + av.z * w2.z + av.w * w3.z;
        acc.w += av.x * w0.w + av.y * w1.w + av.z * w2.w + av.w * w3.w;
    }
    float dv = g_dinv[n];
    acc.x *= dv; acc.y *= dv; acc.z *= dv; acc.w *= dv;
    ((float4*)g_h2)[(long long)n * 4 + f4] = acc;
}

// -------- agg layer2 + final: out = relu(dinv*(sum)+b2) @ Wf + bf
// 4 threads per node, float4 each (16 features), shuffle-reduce the dot.
__global__ __launch_bounds__(256) void k_agg2(const float* __restrict__ b2,
                                              const float* __restrict__ Wf,
                                              const float* __restrict__ bf,
                                              float* __restrict__ out, int N) {
    int idx = blockIdx.x * blockDim.x + threadIdx.x;
    int n = idx >> 2, c = idx & 3;
    if (n >= N) return;
    int beg = g_rowp[n];
    int end = beg + g_cnt[n];
    float4 acc = ((const float4*)g_h2)[(long long)n * 4 + c];   // self term
    for (int j = beg; j < end; j++) {
        int s = g_csr[j];
        float4 v = ((const float4*)g_h2)[(long long)s * 4 + c];
        acc.x += v.x; acc.y += v.y; acc.z += v.z; acc.w += v.w;
    }
    float dv = g_dinv[n];
    float4 bb = ((const float4*)b2)[c];
    float4 w  = ((const float4*)Wf)[c];
    float p = fmaxf(acc.x * dv + bb.x, 0.f) * w.x
            + fmaxf(acc.y * dv + bb.y, 0.f) * w.y
            + fmaxf(acc.z * dv + bb.z, 0.f) * w.z
            + fmaxf(acc.w * dv + bb.w, 0.f) * w.w;
    p += __shfl_xor_sync(0xffffffffu, p, 1);
    p += __shfl_xor_sync(0xffffffffu, p, 2);
    if (c == 0) out[n] = p + __ldg(&bf[0]);
}

// ---------------------------------------------------------------- launcher
extern "C" void kernel_launch(void* const* d_in, const int* in_sizes, int n_in,
                              void* d_out, int out_size) {
    const float* x  = (const float*)d_in[0];
    const void*  ei = d_in[1];
    const float* W1 = (const float*)d_in[2];
    const float* b1 = (const float*)d_in[3];
    const float* W2 = (const float*)d_in[4];
    const float* b2 = (const float*)d_in[5];
    const float* Wf = (const float*)d_in[6];
    const float* bf = (const float*)d_in[7];
    float* out = (float*)d_out;

    int N = in_sizes[0] / 128;   // 100000
    int E = in_sizes[1] / 2;     // 3200000
    int NB = (N + SCAN_B - 1) / SCAN_B;

    k_zero_cnt<<<(N + 255) / 256, 256>>>(N);
    k_detect  <<<1, 1>>>(ei, N);
    k_convert <<<(E + 255) / 256, 256>>>(ei, E);
    k_scan1   <<<NB, SCAN_B>>>(N);
    k_scan2   <<<1, 256>>>(NB);
    k_scan3   <<<(N + 255) / 256, 256>>>(N);
    k_scatter <<<(E + 255) / 256, 256>>>(E);
    k_gemm1   <<<(N + 31) / 32, 256>>>(x, W1, N);
    k_agg1    <<<(N * 8 + 255) / 256, 256>>>(b1, N);
    k_gemm2   <<<(N + 63) / 64, 256>>>(W2, N);
    k_agg2    <<<(N * 4 + 255) / 256, 256>>>(b2, Wf, bf, out, N);
}

// round 4
// speedup vs baseline: 1.3547x; 1.0338x over previous
#include <cuda_runtime.h>

// GCN: 2x GCNConv (sym-norm, self-loops) + ReLU + final linear.
// N=100000, E=3.2M, dims 128->32->16->1.
// CSR-by-dst built per replay (reading edge_index directly, no int32 copy);
// norm factored: features pre-scaled by dinv -> aggregation = gather+sum.

#define NMAX 100000
#define EMAX 3200000
#define SCAN_B 512
#define NBLK ((NMAX + SCAN_B - 1) / SCAN_B)

__device__ int g_is64;
__device__ __align__(16) int   g_csr [EMAX];
__device__ __align__(16) int   g_cnt [NMAX];
__device__ __align__(16) int   g_rowp[NMAX];
__device__ __align__(16) int   g_wcur[NMAX];
__device__ __align__(16) int   g_bsum[NBLK];
__device__ __align__(16) int   g_boff[NBLK];
__device__ __align__(16) float g_dinv[NMAX];
__device__ __align__(16) float g_h1  [NMAX * 32];   // dinv-prescaled x@W1
__device__ __align__(16) float g_a1  [NMAX * 32];   // relu(agg1 + b1)
__device__ __align__(16) float g_h2  [NMAX * 16];   // dinv-prescaled a1@W2

// ------------------------------------------- zero counts + dtype detection
// int32 data read as int64 has a uniform [0,1e5) value in the high word ->
// 16 consecutive in-range int64 reads is conclusive for genuine int64.
__global__ void k_init(const void* ei, int N) {
    int i = blockIdx.x * blockDim.x + threadIdx.x;
    if (i < N) g_cnt[i] = 0;
    if (i == 0) {
        const long long* p = (const long long*)ei;
        int ok = 1;
        for (int k = 0; k < 16; k++) {
            long long v = p[k];
            if (v < 0 || v >= N) ok = 0;
        }
        g_is64 = ok;
    }
}

// ----------------------------------------------------- dst-degree counting
__global__ void k_count(const void* ei, int E) {
    int e = blockIdx.x * blockDim.x + threadIdx.x;
    if (e >= E) return;
    int d = g_is64 ? (int)((const long long*)ei)[(long long)E + e]
                   : ((const int*)ei)[E + e];
    atomicAdd(&g_cnt[d], 1);
}

// --------------------------------------------- prefix scan (shuffle-based)
__global__ __launch_bounds__(SCAN_B) void k_scan1(int N) {
    __shared__ int wsum[SCAN_B / 32];
    int t = threadIdx.x, lane = t & 31, w = t >> 5;
    int i = blockIdx.x * SCAN_B + t;
    int v = (i < N) ? g_cnt[i] : 0;
    int acc = v;
#pragma unroll
    for (int off = 1; off < 32; off <<= 1) {
        int add = __shfl_up_sync(0xffffffffu, acc, off);
        if (lane >= off) acc += add;
    }
    if (lane == 31) wsum[w] = acc;
    __syncthreads();
    if (w == 0) {
        int ws = (lane < SCAN_B / 32) ? wsum[lane] : 0;
        int wa = ws;
#pragma unroll
        for (int off = 1; off < SCAN_B / 32; off <<= 1) {
            int add = __shfl_up_sync(0xffffffffu, wa, off);
            if (lane >= off) wa += add;
        }
        if (lane < SCAN_B / 32) wsum[lane] = wa - ws;   // exclusive
    }
    __syncthreads();
    acc += wsum[w];
    if (i < N) g_rowp[i] = acc - v;                      // block-local exclusive
    if (t == SCAN_B - 1) g_bsum[blockIdx.x] = acc;
}

__global__ __launch_bounds__(256) void k_scan2(int NB) {
    __shared__ int wsum[8];
    int t = threadIdx.x, lane = t & 31, w = t >> 5;
    int v = (t < NB) ? g_bsum[t] : 0;
    int acc = v;
#pragma unroll
    for (int off = 1; off < 32; off <<= 1) {
        int add = __shfl_up_sync(0xffffffffu, acc, off);
        if (lane >= off) acc += add;
    }
    if (lane == 31) wsum[w] = acc;
    __syncthreads();
    if (w == 0) {
        int ws = (lane < 8) ? wsum[lane] : 0;
        int wa = ws;
#pragma unroll
        for (int off = 1; off < 8; off <<= 1) {
            int add = __shfl_up_sync(0xffffffffu, wa, off);
            if (lane >= off) wa += add;
        }
        if (lane < 8) wsum[lane] = wa - ws;
    }
    __syncthreads();
    acc += wsum[w];
    if (t < NB) g_boff[t] = acc - v;
}

__global__ void k_scan3(int N) {
    int i = blockIdx.x * blockDim.x + threadIdx.x;
    if (i < N) {
        int r = g_rowp[i] + g_boff[i / SCAN_B];
        g_rowp[i] = r;
        g_wcur[i] = r;
    }
}

// --------------------------------------------------------- CSR edge scatter
__global__ void k_scatter(const void* ei, int E) {
    int e = blockIdx.x * blockDim.x + threadIdx.x;
    if (e >= E) return;
    int s, d;
    if (g_is64) {
        const long long* p = (const long long*)ei;
        s = (int)p[e];
        d = (int)p[(long long)E + e];
    } else {
        const int* p = (const int*)ei;
        s = p[e];
        d = p[E + e];
    }
    int pos = atomicAdd(&g_wcur[d], 1);
    g_csr[pos] = s;
}

// --------------------------- GEMM1: h1s = dinv * (x @ W1); also write dinv
__global__ __launch_bounds__(256) void k_gemm1(const float* __restrict__ x,
                                               const float* __restrict__ W1,
                                               int N) {
    __shared__ float Ws[128 * 32];
    __shared__ float xs[32 * 129];
    int t = threadIdx.x;
    for (int i = t; i < 128 * 32; i += 256) Ws[i] = W1[i];
    int base = blockIdx.x * 32;
    for (int i = t; i < 32 * 128; i += 256) {
        int n = i >> 7, k = i & 127;
        int node = base + n;
        xs[n * 129 + k] = (node < N) ? x[(long long)node * 128 + k] : 0.0f;
    }
    __syncthreads();

    int f4 = t & 7;
    int n  = t >> 3;
    int node = base + n;

    float4 acc = make_float4(0.f, 0.f, 0.f, 0.f);
    const float4* Ws4 = (const float4*)Ws;
#pragma unroll 8
    for (int k = 0; k < 128; k++) {
        float  xv = xs[n * 129 + k];
        float4 w  = Ws4[k * 8 + f4];
        acc.x += xv * w.x; acc.y += xv * w.y;
        acc.z += xv * w.z; acc.w += xv * w.w;
    }
    if (node < N) {
        float dv = rsqrtf((float)(g_cnt[node] + 1));   // +1 self-loop
        if (f4 == 0) g_dinv[node] = dv;
        acc.x *= dv; acc.y *= dv; acc.z *= dv; acc.w *= dv;
        ((float4*)g_h1)[(long long)node * 8 + f4] = acc;
    }
}

// ----------------- agg layer1: a1 = relu(dinv*(h1s[self]+sum h1s[nbr]) + b1)
// 8 threads/node, float4 each; gather loop unrolled x4 for MLP.
__global__ __launch_bounds__(256) void k_agg1(const float* __restrict__ b1, int N) {
    int idx = blockIdx.x * blockDim.x + threadIdx.x;
    int n = idx >> 3, c = idx & 7;
    if (n >= N) return;
    int beg = g_rowp[n];
    int cnt = g_cnt[n];
    int end = beg + cnt;
    float4 acc = ((const float4*)g_h1)[(long long)n * 8 + c];   // self term
    const float4* h1 = (const float4*)g_h1;
    int j = beg;
    for (; j + 4 <= end; j += 4) {
        int s0 = g_csr[j], s1 = g_csr[j + 1], s2 = g_csr[j + 2], s3 = g_csr[j + 3];
        float4 v0 = h1[(long long)s0 * 8 + c];
        float4 v1 = h1[(long long)s1 * 8 + c];
        float4 v2 = h1[(long long)s2 * 8 + c];
        float4 v3 = h1[(long long)s3 * 8 + c];
        acc.x += v0.x + v1.x + v2.x + v3.x;
        acc.y += v0.y + v1.y + v2.y + v3.y;
        acc.z += v0.z + v1.z + v2.z + v3.z;
        acc.w += v0.w + v1.w + v2.w + v3.w;
    }
    for (; j < end; j++) {
        float4 v = h1[(long long)g_csr[j] * 8 + c];
        acc.x += v.x; acc.y += v.y; acc.z += v.z; acc.w += v.w;
    }
    float dv = g_dinv[n];
    float4 bb = ((const float4*)b1)[c];
    float4 r;
    r.x = fmaxf(acc.x * dv + bb.x, 0.f);
    r.y = fmaxf(acc.y * dv + bb.y, 0.f);
    r.z = fmaxf(acc.z * dv + bb.z, 0.f);
    r.w = fmaxf(acc.w * dv + bb.w, 0.f);
    ((float4*)g_a1)[(long long)n * 8 + c] = r;
}

// --------------------------------- GEMM2: h2s = dinv * (a1 @ W2)
__global__ __launch_bounds__(256) void k_gemm2(const float* __restrict__ W2, int N) {
    __shared__ float Ws[32 * 16];
    int t = threadIdx.x;
    for (int i = t; i < 32 * 16; i += 256) Ws[i] = W2[i];
    __syncthreads();

    int f4 = t & 3;
    int n  = blockIdx.x * 64 + (t >> 2);
    if (n >= N) return;

    float4 acc = make_float4(0.f, 0.f, 0.f, 0.f);
    const float4* a1r = (const float4*)(g_a1 + (long long)n * 32);
    const float4* Ws4 = (const float4*)Ws;
#pragma unroll
    for (int k4 = 0; k4 < 8; k4++) {
        float4 av = a1r[k4];
        float4 w0 = Ws4[(k4 * 4 + 0) * 4 + f4];
        float4 w1 = Ws4[(k4 * 4 + 1) * 4 + f4];
        float4 w2 = Ws4[(k4 * 4 + 2) * 4 + f4];
        float4 w3 = Ws4[(k4 * 4 + 3) * 4 + f4];
        acc.x += av.x * w0.x + av.y * w1.x + av.z * w2.x + av.w * w3.x;
        acc.y += av.x * w0.y + av.y * w1.y + av.z * w2.y + av.w * w3.y;
        acc.z += av.x * w0.z + av.y * w1.z + av.z * w2.z + av.w * w3.z;
        acc.w += av.x * w0.w + av.y * w1.w + av.z * w2.w + av.w * w3.w;
    }
    float dv = g_dinv[n];
    acc.x *= dv; acc.y *= dv; acc.z *= dv; acc.w *= dv;
    ((float4*)g_h2)[(long long)n * 4 + f4] = acc;
}

// -------- agg layer2 + final: out = (relu(dinv*sum + b2)) @ Wf + bf
// 4 threads/node, float4 each; gather loop unrolled x4.
__global__ __launch_bounds__(256) void k_agg2(const float* __restrict__ b2,
                                              const float* __restrict__ Wf,
                                              const float* __restrict__ bf,
                                              float* __restrict__ out, int N) {
    int idx = blockIdx.x * blockDim.x + threadIdx.x;
    int n = idx >> 2, c = idx & 3;
    if (n >= N) return;
    int beg = g_rowp[n];
    int end = beg + g_cnt[n];
    float4 acc = ((const float4*)g_h2)[(long long)n * 4 + c];   // self term
    const float4* h2 = (const float4*)g_h2;
    int j = beg;
    for (; j + 4 <= end; j += 4) {
        int s0 = g_csr[j], s1 = g_csr[j + 1], s2 = g_csr[j + 2], s3 = g_csr[j + 3];
        float4 v0 = h2[(long long)s0 * 4 + c];
        float4 v1 = h2[(long long)s1 * 4 + c];
        float4 v2 = h2[(long long)s2 * 4 + c];
        float4 v3 = h2[(long long)s3 * 4 + c];
        acc.x += v0.x + v1.x + v2.x + v3.x;
        acc.y += v0.y + v1.y + v2.y + v3.y;
        acc.z += v0.z + v1.z + v2.z + v3.z;
        acc.w += v0.w + v1.w + v2.w + v3.w;
    }
    for (; j < end; j++) {
        float4 v = h2[(long long)g_csr[j] * 4 + c];
        acc.x += v.x; acc.y += v.y; acc.z += v.z; acc.w += v.w;
    }
    float dv = g_dinv[n];
    float4 bb = ((const float4*)b2)[c];
    float4 w  = ((const float4*)Wf)[c];
    float p = fmaxf(acc.x * dv + bb.x, 0.f) * w.x
            + fmaxf(acc.y * dv + bb.y, 0.f) * w.y
            + fmaxf(acc.z * dv + bb.z, 0.f) * w.z
            + fmaxf(acc.w * dv + bb.w, 0.f) * w.w;
    p += __shfl_xor_sync(0xffffffffu, p, 1);
    p += __shfl_xor_sync(0xffffffffu, p, 2);
    if (c == 0) out[n] = p + __ldg(&bf[0]);
}

// ---------------------------------------------------------------- launcher
extern "C" void kernel_launch(void* const* d_in, const int* in_sizes, int n_in,
                              void* d_out, int out_size) {
    const float* x  = (const float*)d_in[0];
    const void*  ei = d_in[1];
    const float* W1 = (const float*)d_in[2];
    const float* b1 = (const float*)d_in[3];
    const float* W2 = (const float*)d_in[4];
    const float* b2 = (const float*)d_in[5];
    const float* Wf = (const float*)d_in[6];
    const float* bf = (const float*)d_in[7];
    float* out = (float*)d_out;

    int N = in_sizes[0] / 128;   // 100000
    int E = in_sizes[1] / 2;     // 3200000
    int NB = (N + SCAN_B - 1) / SCAN_B;

    k_init    <<<(N + 255) / 256, 256>>>(ei, N);
    k_count   <<<(E + 255) / 256, 256>>>(ei, E);
    k_scan1   <<<NB, SCAN_B>>>(N);
    k_scan2   <<<1, 256>>>(NB);
    k_scan3   <<<(N + 255) / 256, 256>>>(N);
    k_scatter <<<(E + 255) / 256, 256>>>(ei, E);
    k_gemm1   <<<(N + 31) / 32, 256>>>(x, W1, N);
    k_agg1    <<<(N * 8 + 255) / 256, 256>>>(b1, N);
    k_gemm2   <<<(N + 63) / 64, 256>>>(W2, N);
    k_agg2    <<<(N * 4 + 255) / 256, 256>>>(b2, Wf, bf, out, N);
}